// round 3
// baseline (speedup 1.0000x reference)
#include <cuda_runtime.h>
#include <cuda_bf16.h>
#include <mma.h>
#include <cstdint>
#include <cstddef>

using namespace nvcuda;

#define BATCH 64
#define TLEN  512
#define EMBD  512
#define HID   1024
#define G4    4096
#define NTAG  10
#define ROWS  (BATCH*TLEN)          // 32768
#define RBLK  128                   // persistent blocks in recurrent kernel

// smem layout of recurrent kernel (floats):
//  Ws [32][1032], As [64][72], Gs [64][36], Cs [512], Bs [32], Ts [64]
#define RW_PITCH 1032
#define RA_PITCH 72
#define RG_PITCH 36
#define RECUR_SMEM_FLOATS (32*RW_PITCH + 64*RA_PITCH + 64*RG_PITCH + 512 + 32 + 64)
#define RECUR_SMEM_BYTES  (RECUR_SMEM_FLOATS * 4)

// ---------------- device scratch (static: no allocations allowed) ----------------
__device__ float g_seq0[(size_t)ROWS*EMBD];     // embeddings, t-major rows (t*64+b)
__device__ float g_xp  [(size_t)ROWS*G4];       // x_proj scratch (reused by both layers)
__device__ float g_hseq[(size_t)ROWS*HID];      // layer-0 hidden sequence
__device__ float g_h[2][BATCH*HID];             // double-buffered recurrent h
__device__ float g_lasth[BATCH*HID];            // layer-1 h at t = lens-1
__device__ float g_Wih0p[(size_t)G4*EMBD];      // gate-permuted, tf32-rounded weights
__device__ float g_Whh0p[(size_t)G4*HID];
__device__ float g_Wih1p[(size_t)G4*HID];
__device__ float g_Whh1p[(size_t)G4*HID];
__device__ float g_b0p[G4];
__device__ float g_b1p[G4];
__device__ int   g_tt[BATCH];                   // target timestep per batch (lens-1 mod T)
__device__ unsigned g_barcnt = 0;               // monotonic grid-barrier ticket counter

// ---------------- grid barrier: monotonic ticket scheme ----------------
// Invariant: g_barcnt is always a multiple of RBLK between kernels (every
// launch completes whole barriers of RBLK arrivals), so the tickets of
// barrier k within a launch occupy [base+128k, base+128k+127] and
// target = (ticket/128 + 1)*128 needs no per-launch bookkeeping.
__device__ __forceinline__ void grid_barrier() {
    __syncthreads();
    if (threadIdx.x == 0) {
        __threadfence();                               // release our block's writes
        unsigned t = atomicAdd(&g_barcnt, 1u);
        unsigned target = ((t >> 7) + 1u) << 7;
        while ((int)(*(volatile unsigned*)&g_barcnt - target) < 0) {}
        __threadfence();                               // acquire
    }
    __syncthreads();
}

// ---------------- preprocessing ----------------
// Permute gate rows: out row 4*j+g  <-  in row g*HID+j, round weights to tf32.
__global__ void permute_kernel(const float* __restrict__ Wih0, const float* __restrict__ Whh0,
                               const float* __restrict__ b0,
                               const float* __restrict__ Wih1, const float* __restrict__ Whh1,
                               const float* __restrict__ b1) {
    int p = blockIdx.x;                 // 0..4095
    int j = p >> 2, q = p & 3;
    size_t src = (size_t)(q * HID + j);
    for (int d = threadIdx.x; d < EMBD; d += blockDim.x)
        g_Wih0p[(size_t)p*EMBD + d] = wmma::__float_to_tf32(Wih0[src*EMBD + d]);
    for (int d = threadIdx.x; d < HID; d += blockDim.x) {
        g_Whh0p[(size_t)p*HID + d] = wmma::__float_to_tf32(Whh0[src*HID + d]);
        g_Wih1p[(size_t)p*HID + d] = wmma::__float_to_tf32(Wih1[src*HID + d]);
        g_Whh1p[(size_t)p*HID + d] = wmma::__float_to_tf32(Whh1[src*HID + d]);
    }
    if (threadIdx.x == 0) { g_b0p[p] = b0[src]; g_b1p[p] = b1[src]; }
}

// Embedding gather into t-major layout: row r = t*64 + b
__global__ void embed_kernel(const int* __restrict__ x, const float* __restrict__ emb) {
    int r = blockIdx.x;
    int b = r & 63, t = r >> 6;
    int tok = x[b * TLEN + t];
    const float4* src = (const float4*)&emb[(size_t)tok * EMBD];
    float4* dst = (float4*)&g_seq0[(size_t)r * EMBD];
    dst[threadIdx.x] = src[threadIdx.x];       // block = 128 threads = 128 float4
}

// lens + target timestep
__global__ void lens_kernel(const int* __restrict__ x) {
    __shared__ int red[8];
    int b = blockIdx.x;
    int c = 0;
    for (int t = threadIdx.x; t < TLEN; t += 256) c += (x[b * TLEN + t] == 0);
    #pragma unroll
    for (int o = 16; o > 0; o >>= 1) c += __shfl_down_sync(0xffffffffu, c, o);
    if ((threadIdx.x & 31) == 0) red[threadIdx.x >> 5] = c;
    __syncthreads();
    if (threadIdx.x == 0) {
        int tot = 0;
        #pragma unroll
        for (int w = 0; w < 8; w++) tot += red[w];
        int tt = TLEN - tot - 1;          // lens-1
        if (tt < 0) tt += TLEN;           // wrap like Python negative index
        g_tt[b] = tt;
    }
}

// ---------------- x_proj GEMM: out[r][p] = sum_k A[r][k] * W[p][k] ----------------
// Block tile 128(M) x 64(N), K-chunk 32, 8 warps each 32x32.
#define XP_BM 128
#define XP_BN 64
#define XP_BK 32
#define XP_AP 40
#define XP_BP 40

__global__ void __launch_bounds__(256) xproj_kernel(const float* __restrict__ A,
                                                    const float* __restrict__ W,
                                                    float* __restrict__ out, int K) {
    __shared__ float As[XP_BM][XP_AP];
    __shared__ float Bs[XP_BN][XP_BP];
    int tid = threadIdx.x;
    int warp = tid >> 5;
    int m0 = blockIdx.y * XP_BM;
    int n0 = blockIdx.x * XP_BN;
    int wm = (warp >> 1) * 32;    // 0,32,64,96
    int wn = (warp & 1) * 32;     // 0,32

    wmma::fragment<wmma::accumulator, 16, 16, 8, float> acc[2][2];
    #pragma unroll
    for (int i = 0; i < 2; i++)
        #pragma unroll
        for (int j = 0; j < 2; j++) wmma::fill_fragment(acc[i][j], 0.0f);

    int ar = tid >> 3;            // 0..31: row within a 32-row pass
    int ak = (tid & 7) * 4;       // float4 start col within chunk

    for (int k0 = 0; k0 < K; k0 += XP_BK) {
        __syncthreads();
        #pragma unroll
        for (int p = 0; p < 4; p++) {              // A: 128 rows
            int r = p * 32 + ar;
            float4 v = *(const float4*)&A[(size_t)(m0 + r) * K + k0 + ak];
            As[r][ak + 0] = wmma::__float_to_tf32(v.x);
            As[r][ak + 1] = wmma::__float_to_tf32(v.y);
            As[r][ak + 2] = wmma::__float_to_tf32(v.z);
            As[r][ak + 3] = wmma::__float_to_tf32(v.w);
        }
        #pragma unroll
        for (int p = 0; p < 2; p++) {              // B: 64 rows (pre-rounded weights)
            int r = p * 32 + ar;
            float4 v = *(const float4*)&W[(size_t)(n0 + r) * K + k0 + ak];
            *(float4*)&Bs[r][ak] = v;
        }
        __syncthreads();
        #pragma unroll
        for (int kk = 0; kk < XP_BK; kk += 8) {
            wmma::fragment<wmma::matrix_a, 16, 16, 8, wmma::precision::tf32, wmma::row_major> af[2];
            wmma::fragment<wmma::matrix_b, 16, 16, 8, wmma::precision::tf32, wmma::col_major> bf[2];
            wmma::load_matrix_sync(af[0], &As[wm][kk], XP_AP);
            wmma::load_matrix_sync(af[1], &As[wm + 16][kk], XP_AP);
            wmma::load_matrix_sync(bf[0], &Bs[wn][kk], XP_BP);
            wmma::load_matrix_sync(bf[1], &Bs[wn + 16][kk], XP_BP);
            #pragma unroll
            for (int i = 0; i < 2; i++)
                #pragma unroll
                for (int j = 0; j < 2; j++)
                    wmma::mma_sync(acc[i][j], af[i], bf[j], acc[i][j]);
        }
    }
    #pragma unroll
    for (int i = 0; i < 2; i++)
        #pragma unroll
        for (int j = 0; j < 2; j++)
            wmma::store_matrix_sync(&out[(size_t)(m0 + wm + 16*i) * G4 + n0 + wn + 16*j],
                                    acc[i][j], G4, wmma::mem_row_major);
}

// ---------------- persistent recurrent kernel ----------------
// 128 blocks; block bk owns permuted gate rows [32*bk, 32*bk+32) = hidden units
// j in [8*bk, 8*bk+8). Per step: gates = xp(t) + h_prev @ Whh_slice^T + b, then
// fused LSTM pointwise, one grid barrier.
__global__ void __launch_bounds__(256) recur_kernel(const float* __restrict__ Whh,
                                                    const float* __restrict__ bias,
                                                    const float* __restrict__ xp,
                                                    int mode) {
    extern __shared__ float sm[];
    float* Ws = sm;                                   // [32][1032] weight slice
    float* As = Ws + 32 * RW_PITCH;                   // [64][72]   h chunk
    float* Gs = As + 64 * RA_PITCH;                   // [64][36]   gates tile
    float* Cs = Gs + 64 * RG_PITCH;                   // [512]      cell state
    float* Bs = Cs + 512;                             // [32]       bias slice
    int*   Ts = (int*)(Bs + 32);                      // [64]       target t per batch

    int tid = threadIdx.x, warp = tid >> 5;
    int bk = blockIdx.x;

    // Stage Whh slice rows [32*bk, 32*bk+32), full K=1024 (already tf32-rounded).
    for (int i = tid; i < 32 * 256; i += 256) {       // 256 float4 per row
        int r = i >> 8;
        int c4 = (i & 255) << 2;
        float4 v = *(const float4*)&Whh[((size_t)(32 * bk + r)) * HID + c4];
        *(float4*)&Ws[r * RW_PITCH + c4] = v;
    }
    if (tid < 32) Bs[tid] = bias[32 * bk + tid];
    if (tid < 64) Ts[tid] = g_tt[tid];
    for (int i = tid; i < 512; i += 256) Cs[i] = 0.0f;
    {   // zero this block's slice of g_h[0]
        int b = tid >> 2, jj2 = (tid & 3) * 2;
        g_h[0][b * HID + 8 * bk + jj2]     = 0.0f;
        g_h[0][b * HID + 8 * bk + jj2 + 1] = 0.0f;
    }
    grid_barrier();                                   // h0 zeroed everywhere

    int wm = (warp & 3) * 16;                         // batch rows
    int wn = (warp >> 2) * 16;                        // gate cols (of 32)

    for (int t = 0; t < TLEN; t++) {
        const float* hprev = g_h[t & 1];
        float* hnext = g_h[(t + 1) & 1];

        wmma::fragment<wmma::accumulator, 16, 16, 8, float> acc;
        wmma::fill_fragment(acc, 0.0f);

        // K loop: 16 chunks of 64, register-prefetched staging of h.
        float4 pre[4];
        #pragma unroll
        for (int p = 0; p < 4; p++) {
            int q = tid + 256 * p;
            int r = q >> 4;
            int c4 = (q & 15) << 2;
            pre[p] = __ldcg((const float4*)&hprev[(size_t)r * HID + c4]);
        }
        for (int ch = 0; ch < 16; ch++) {
            __syncthreads();
            #pragma unroll
            for (int p = 0; p < 4; p++) {
                int q = tid + 256 * p;
                int r = q >> 4;
                int c4 = (q & 15) << 2;
                As[r * RA_PITCH + c4 + 0] = wmma::__float_to_tf32(pre[p].x);
                As[r * RA_PITCH + c4 + 1] = wmma::__float_to_tf32(pre[p].y);
                As[r * RA_PITCH + c4 + 2] = wmma::__float_to_tf32(pre[p].z);
                As[r * RA_PITCH + c4 + 3] = wmma::__float_to_tf32(pre[p].w);
            }
            if (ch < 15) {
                #pragma unroll
                for (int p = 0; p < 4; p++) {
                    int q = tid + 256 * p;
                    int r = q >> 4;
                    int c4 = (q & 15) << 2;
                    pre[p] = __ldcg((const float4*)&hprev[(size_t)r * HID + (ch + 1) * 64 + c4]);
                }
            }
            __syncthreads();
            #pragma unroll
            for (int kk = 0; kk < 64; kk += 8) {
                wmma::fragment<wmma::matrix_a, 16, 16, 8, wmma::precision::tf32, wmma::row_major> af;
                wmma::fragment<wmma::matrix_b, 16, 16, 8, wmma::precision::tf32, wmma::col_major> bf;
                wmma::load_matrix_sync(af, &As[wm * RA_PITCH + kk], RA_PITCH);
                wmma::load_matrix_sync(bf, &Ws[wn * RW_PITCH + ch * 64 + kk], RW_PITCH);
                wmma::mma_sync(acc, af, bf, acc);
            }
        }
        wmma::store_matrix_sync(&Gs[wm * RG_PITCH + wn], acc, RG_PITCH, wmma::mem_row_major);
        __syncthreads();

        // Fused pointwise: 512 (b, jj) pairs, 2 per thread; idx = b*8 + jj.
        #pragma unroll
        for (int it = 0; it < 2; it++) {
            int idx = tid + it * 256;
            int b = idx >> 3, jj = idx & 7;
            const float* gr = &Gs[b * RG_PITCH + jj * 4];
            const float* xr = &xp[((size_t)(t * 64 + b)) * G4 + 32 * bk + jj * 4];
            float gi = gr[0] + xr[0] + Bs[jj * 4 + 0];
            float gf = gr[1] + xr[1] + Bs[jj * 4 + 1];
            float gg = gr[2] + xr[2] + Bs[jj * 4 + 2];
            float go = gr[3] + xr[3] + Bs[jj * 4 + 3];
            float c = Cs[idx];
            float si = 1.0f / (1.0f + __expf(-gi));
            float sf = 1.0f / (1.0f + __expf(-gf));
            float so = 1.0f / (1.0f + __expf(-go));
            c = sf * c + si * tanhf(gg);
            Cs[idx] = c;
            float h = so * tanhf(c);
            hnext[(size_t)b * HID + 8 * bk + jj] = h;
            if (mode == 0)
                g_hseq[((size_t)(t * 64 + b)) * HID + 8 * bk + jj] = h;
            else if (t == Ts[b])
                g_lasth[(size_t)b * HID + 8 * bk + jj] = h;
        }
        grid_barrier();
    }
}

// ---------------- output projection: out[b][tag] = lasth[b] . Wout[tag] + bout ----------------
__global__ void out_kernel(const float* __restrict__ Wout, const float* __restrict__ bout,
                           float* __restrict__ out) {
    __shared__ float red[4];
    int b = blockIdx.x, tag = blockIdx.y;
    float s = 0.0f;
    for (int k = threadIdx.x; k < HID; k += 128)
        s += g_lasth[b * HID + k] * Wout[tag * HID + k];
    #pragma unroll
    for (int o = 16; o > 0; o >>= 1) s += __shfl_down_sync(0xffffffffu, s, o);
    if ((threadIdx.x & 31) == 0) red[threadIdx.x >> 5] = s;
    __syncthreads();
    if (threadIdx.x == 0)
        out[b * NTAG + tag] = red[0] + red[1] + red[2] + red[3] + bout[tag];
}

// ---------------- launch ----------------
extern "C" void kernel_launch(void* const* d_in, const int* in_sizes, int n_in,
                              void* d_out, int out_size) {
    const int*   x    = (const int*)d_in[0];
    const float* emb  = (const float*)d_in[1];
    const float* Wih0 = (const float*)d_in[2];
    const float* Whh0 = (const float*)d_in[3];
    const float* b0   = (const float*)d_in[4];
    const float* Wih1 = (const float*)d_in[5];
    const float* Whh1 = (const float*)d_in[6];
    const float* b1   = (const float*)d_in[7];
    const float* Wout = (const float*)d_in[8];
    const float* bout = (const float*)d_in[9];
    float* out = (float*)d_out;

    cudaFuncSetAttribute(recur_kernel, cudaFuncAttributeMaxDynamicSharedMemorySize,
                         RECUR_SMEM_BYTES);

    float *p_seq0, *p_hseq, *p_xp, *pWih0, *pWih1, *pWhh0, *pWhh1, *pb0, *pb1;
    cudaGetSymbolAddress((void**)&p_seq0, g_seq0);
    cudaGetSymbolAddress((void**)&p_hseq, g_hseq);
    cudaGetSymbolAddress((void**)&p_xp,   g_xp);
    cudaGetSymbolAddress((void**)&pWih0,  g_Wih0p);
    cudaGetSymbolAddress((void**)&pWih1,  g_Wih1p);
    cudaGetSymbolAddress((void**)&pWhh0,  g_Whh0p);
    cudaGetSymbolAddress((void**)&pWhh1,  g_Whh1p);
    cudaGetSymbolAddress((void**)&pb0,    g_b0p);
    cudaGetSymbolAddress((void**)&pb1,    g_b1p);

    permute_kernel<<<G4, 256>>>(Wih0, Whh0, b0, Wih1, Whh1, b1);
    embed_kernel<<<ROWS, 128>>>(x, emb);
    lens_kernel<<<BATCH, 256>>>(x);

    dim3 xg(G4 / XP_BN, ROWS / XP_BM);                 // (64, 256)

    // Layer 0
    xproj_kernel<<<xg, 256>>>(p_seq0, pWih0, p_xp, EMBD);
    recur_kernel<<<RBLK, 256, RECUR_SMEM_BYTES>>>(pWhh0, pb0, p_xp, 0);

    // Layer 1
    xproj_kernel<<<xg, 256>>>(p_hseq, pWih1, p_xp, HID);
    recur_kernel<<<RBLK, 256, RECUR_SMEM_BYTES>>>(pWhh1, pb1, p_xp, 1);

    // Output head
    out_kernel<<<dim3(BATCH, NTAG), 128>>>(Wout, bout, out);
}